// round 12
// baseline (speedup 1.0000x reference)
#include <cuda_runtime.h>

// Problem constants
#define AP 48        // paths
#define LL 64        // length
#define DD 64        // channels
#define MM 63        // L-1 (increments)
#define PER_GRAM (AP*AP)          // 2304

#define NPB 96                    // 48 X blocks + 48 Y blocks (64 padded rows)
#define ROWS (NPB*64)             // 6144
#define NTILE 48                  // tiles per dim (128 rows each)
#define NTRI (NTILE*(NTILE+1)/2)  // 1176 upper-triangle tiles
#define HALF_TILES (NTRI/2)       // 588 tiles per phase (38.5 MB inc -> L2)
#define NK2 (NTRI*4)              // 4704 (tile, sub) result slots
#define BLK_ELEMS (64*64)

#define PDE_CTAS_HALF (HALF_TILES/2)   // 294 CTAs x 8 warps (2 tiles/CTA)

// Static scratch (no allocation allowed). g_Ks zero-init at module load;
// inactive diagonal sub-slots are never written and stay 0 (deterministic).
__device__ float g_dZ[(size_t)ROWS * 64];            // 1.5 MB padded increments
__device__ float g_inc[(size_t)NTRI * 4 * BLK_ELEMS];// 77 MB, halves used in turn
__device__ float g_Ks[NK2];
__device__ unsigned g_ctr;                           // last-CTA counter (phase B)

// gemm smem (proven layout): A^T [k][m] stride 129, B^T [k][n] stride 130
#define SA_STRIDE 129
#define SB_STRIDE 130
#define SMEM_FLOATS (64*SA_STRIDE + 64*SB_STRIDE)
#define SMEM_BYTES (SMEM_FLOATS * sizeof(float))     // 66304 B

// ---------------------------------------------------------------------------
// Kernel 0: padded increments dZ[blk*64+i][d]; row i=63 zeroed.
// ---------------------------------------------------------------------------
__global__ void __launch_bounds__(256) dz_kernel(
    const float* __restrict__ X, const float* __restrict__ Y)
{
    const int idx = blockIdx.x * 256 + threadIdx.x;   // float4 index
    const int row = idx >> 4;
    const int d4  = idx & 15;
    const int blk = row >> 6;
    const int i   = row & 63;

    float4 v = make_float4(0.f, 0.f, 0.f, 0.f);
    if (i < MM) {
        const float* src = (blk < AP) ? (X + blk * (LL * DD))
                                      : (Y + (blk - AP) * (LL * DD));
        const float4 hi = *reinterpret_cast<const float4*>(src + (i + 1) * DD + 4 * d4);
        const float4 lo = *reinterpret_cast<const float4*>(src + i * DD + 4 * d4);
        v = make_float4(hi.x - lo.x, hi.y - lo.y, hi.z - lo.z, hi.w - lo.w);
    }
    *reinterpret_cast<float4*>(g_dZ + (size_t)row * 64 + 4 * d4) = v;
}

// ---------------------------------------------------------------------------
// Kernel 1: SYRK tile batch. 128x128x64 tiles (u >= t), packed fma.rn.f32x2.
// Processes tiles [tile_base, tile_base + gridDim.x). Epilogue scatters the
// 64x64 sub-blocks into g_inc[tile*4 + sub].
// ---------------------------------------------------------------------------
__global__ void __launch_bounds__(256, 2) gemm_kernel(int tile_base)
{
    extern __shared__ float smem[];
    float* sA = smem;                       // [64][SA_STRIDE]
    float* sB = smem + 64 * SA_STRIDE;      // [64][SB_STRIDE]

    const int tile = tile_base + blockIdx.x;
    int q = tile;
    int t = 0;
    while (q >= NTILE - t) { q -= NTILE - t; t++; }
    const int u = t + q;

    const int gr0 = t * 128;
    const int gc0 = u * 128;
    const int tid = threadIdx.x;

    for (int idx = tid; idx < 128 * 64; idx += 256) {
        const int m = idx >> 6;
        const int k = idx & 63;
        sA[k * SA_STRIDE + m] = g_dZ[(size_t)(gr0 + m) * 64 + k];
        sB[k * SB_STRIDE + m] = g_dZ[(size_t)(gc0 + m) * 64 + k];
    }
    __syncthreads();

    const int ty = tid >> 4;     // 0..15
    const int tx = tid & 15;     // 0..15
    const int m0 = ty * 8;
    const int n0 = 2 * tx;

    unsigned long long acc[8][4];
#pragma unroll
    for (int i = 0; i < 8; i++)
#pragma unroll
        for (int j = 0; j < 4; j++) acc[i][j] = 0ull;

    const float* sA_ = sA + m0;
    const float* sB_ = sB + n0;

#pragma unroll 8
    for (int k = 0; k < 64; k++) {
        unsigned long long aa[8], bb[4];
#pragma unroll
        for (int i = 0; i < 8; i++) {
            const float a = sA_[k * SA_STRIDE + i];
            asm("mov.b64 %0, {%1, %1};" : "=l"(aa[i]) : "f"(a));
        }
#pragma unroll
        for (int j = 0; j < 4; j++)
            bb[j] = *reinterpret_cast<const unsigned long long*>(
                        &sB_[k * SB_STRIDE + 32 * j]);
#pragma unroll
        for (int i = 0; i < 8; i++)
#pragma unroll
            for (int j = 0; j < 4; j++)
                asm("fma.rn.f32x2 %0, %1, %2, %0;"
                    : "+l"(acc[i][j]) : "l"(aa[i]), "l"(bb[j]));
    }

    // epilogue: rows m0..m0+7 lie in sub-row r = ty>>3; j<2 -> c=0, j>=2 -> c=1
    const int r   = ty >> 3;
    const int li0 = m0 & 63;

#pragma unroll
    for (int c = 0; c < 2; c++) {
        const int pa = 2 * t + r;
        const int pb = 2 * u + c;
        if (pa > pb) continue;            // only (r=1,c=0) on diagonal tiles
        float* dst = g_inc + ((size_t)tile * 4 + r * 2 + c) * BLK_ELEMS;
#pragma unroll
        for (int i = 0; i < 8; i++) {
            float* row = dst + (li0 + i) * 64 + n0;
#pragma unroll
            for (int j = 0; j < 2; j++)
                *reinterpret_cast<float2*>(row + 32 * j) =
                    *reinterpret_cast<float2*>(&acc[i][2 * c + j]);
        }
    }
}

// ---------------------------------------------------------------------------
// Kernel 2: Goursat PDE scan, one warp per (tile, sub) slot, reading the
// just-written (L2-resident) inc half. 4-deep row prefetch ring.
// Row update is a prefix sum: new[j+1] = 1 + sum_{k<=j} c[k],
//   c[j] = prev[j+1] + prev[j]*(inc[i,j]-1).
// Final pde launch (do_reduce=1) also does the last-CTA global reduction.
// ---------------------------------------------------------------------------
__global__ void __launch_bounds__(256) pde_kernel(
    const float* __restrict__ X, const float* __restrict__ Y,
    float* __restrict__ out, int tile_base, int do_reduce)
{
    const int warp = (blockIdx.x << 3) | (threadIdx.x >> 5);
    const int lane = threadIdx.x & 31;
    const bool lastl = (lane == 31);

    {
        const int tile = tile_base + (warp >> 2);
        const int sub  = warp & 3;
        const int r = sub >> 1, c = sub & 1;

        int q = tile;
        int t = 0;
        while (q >= NTILE - t) { q -= NTILE - t; t++; }
        const int u = t + q;
        const int pa = 2 * t + r;
        const int pb = 2 * u + c;

        if (pa <= pb) {
            float w;
            if (pa < AP && pb >= AP) w = -2.0f / (float)PER_GRAM;       // XY
            else w = ((pa == pb) ? 1.0f : 2.0f) / (float)PER_GRAM;      // XX/YY

            const float* __restrict__ base =
                g_inc + ((size_t)tile * 4 + sub) * BLK_ELEMS + 2 * lane;

            float p0 = 1.0f, p1 = 1.0f;

            float2 buf[4];
#pragma unroll
            for (int k = 0; k < 4; k++)
                buf[k] = __ldg(reinterpret_cast<const float2*>(base + k * 64));

#pragma unroll 4
            for (int i = 0; i < MM; i++) {
                const float2 inc = buf[i & 3];
                if (i + 4 < MM)
                    buf[i & 3] = __ldg(reinterpret_cast<const float2*>(
                                           base + (i + 4) * 64));

                const float p2 = __shfl_down_sync(0xffffffffu, p0, 1);

                const float c0 = fmaf(p0, inc.x - 1.0f, p1);
                const float c1 = lastl ? 0.0f : fmaf(p1, inc.y - 1.0f, p2);

                const float sm = c0 + c1;
                float tc = sm;
#pragma unroll
                for (int off = 1; off < 32; off <<= 1) {
                    const float uu = __shfl_up_sync(0xffffffffu, tc, off);
                    if (lane >= off) tc += uu;
                }
                p0 = 1.0f + (tc - sm);        // exclusive scan
                p1 = p0 + c0;
            }

            if (lastl) g_Ks[tile * 4 + sub] = w * p1;   // weighted K[63][63]
        }
    }

    if (!do_reduce) return;

    // ---- fused final reduction: last CTA sums g_Ks + start term -----------
    __threadfence();
    __syncthreads();
    __shared__ bool s_is_last;
    if (threadIdx.x == 0)
        s_is_last = (atomicAdd(&g_ctr, 1u) == (unsigned)(gridDim.x - 1));
    __syncthreads();
    if (!s_is_last) return;

    __shared__ float sdata[256];
    const int tid = threadIdx.x;
    float s = 0.0f;
    for (int p = tid; p < NK2; p += 256) s += __ldcg(&g_Ks[p]);

    float s2 = 0.0f;
    for (int idx = tid; idx < AP * DD; idx += 256) {
        const int aa = idx >> 6;
        const int d  = idx & 63;
        const float diff = X[aa * (LL * DD) + d] - Y[aa * (LL * DD) + d];
        s2 = fmaf(diff, diff, s2);
    }
    s += s2 * (1.0f / (float)(AP * DD));

    sdata[tid] = s;
    __syncthreads();
    for (int k = 128; k > 0; k >>= 1) {
        if (tid < k) sdata[tid] += sdata[tid + k];
        __syncthreads();
    }
    if (tid == 0) {
        out[0] = sdata[0];
        g_ctr = 0u;              // reset for next graph replay
    }
}

// ---------------------------------------------------------------------------
extern "C" void kernel_launch(void* const* d_in, const int* in_sizes, int n_in,
                              void* d_out, int out_size)
{
    const float* X = (const float*)d_in[0];
    const float* Y = (const float*)d_in[1];
    float* out = (float*)d_out;

    static bool attr_done = false;
    if (!attr_done) {
        cudaFuncSetAttribute(gemm_kernel,
                             cudaFuncAttributeMaxDynamicSharedMemorySize,
                             SMEM_BYTES);
        attr_done = true;
    }

    dz_kernel<<<384, 256>>>(X, Y);
    // phase A: first half of tiles; inc half stays L2-resident for its pde
    gemm_kernel<<<HALF_TILES, 256, SMEM_BYTES>>>(0);
    pde_kernel<<<PDE_CTAS_HALF, 256>>>(X, Y, out, 0, 0);
    // phase B: second half + fused final reduction
    gemm_kernel<<<HALF_TILES, 256, SMEM_BYTES>>>(HALF_TILES);
    pde_kernel<<<PDE_CTAS_HALF, 256>>>(X, Y, out, HALF_TILES, 1);
}

// round 13
// speedup vs baseline: 1.0295x; 1.0295x over previous
#include <cuda_runtime.h>

// Problem constants
#define AP 48        // paths
#define LL 64        // length
#define DD 64        // channels
#define MM 63        // L-1 (increments)
#define PER_GRAM (AP*AP)          // 2304

#define NPB 96                    // 48 X blocks + 48 Y blocks (64 padded rows)
#define ROWS (NPB*64)             // 6144
#define NTILE 48                  // tiles per dim (128 rows each)
#define NTRI (NTILE*(NTILE+1)/2)  // 1176 upper-triangle tiles
#define NK2 (NTRI*4)              // 4704 (tile, sub) result slots
#define BLK_ELEMS (64*64)

#define PDE_CTAS (NTRI/2)         // 588 consumer CTAs (8 warps = 2 tiles x 4 subs)
#define TOTAL_CTAS (NTRI + PDE_CTAS)

// Static scratch (no allocation allowed). g_Ks zero-init at module load;
// inactive diagonal sub-slots are never written and stay 0 (deterministic).
__device__ float g_dZ[(size_t)ROWS * 64];             // 1.5 MB padded increments
__device__ float g_inc[(size_t)NTRI * 4 * BLK_ELEMS]; // 77 MB (consumed from L2)
__device__ float g_Ks[NK2];
__device__ unsigned g_flag[NTRI];                     // per-tile ready flags
__device__ unsigned g_ctr;                            // pde-CTA counter

// gemm smem (proven layout): A^T [k][m] stride 129, B^T [k][n] stride 130
#define SA_STRIDE 129
#define SB_STRIDE 130
#define SMEM_FLOATS (64*SA_STRIDE + 64*SB_STRIDE)
#define SMEM_BYTES (SMEM_FLOATS * sizeof(float))      // 66304 B

// ---------------------------------------------------------------------------
// Kernel 0: padded increments dZ + reset flags/counter for this replay.
// ---------------------------------------------------------------------------
__global__ void __launch_bounds__(256) dz_kernel(
    const float* __restrict__ X, const float* __restrict__ Y)
{
    const int gidx = blockIdx.x * 256 + threadIdx.x;
    if (gidx < NTRI) g_flag[gidx] = 0u;
    if (gidx == 0) g_ctr = 0u;

    const int row = gidx >> 4;      // padded row
    const int d4  = gidx & 15;      // float4 within row
    const int blk = row >> 6;
    const int i   = row & 63;

    float4 v = make_float4(0.f, 0.f, 0.f, 0.f);
    if (i < MM) {
        const float* src = (blk < AP) ? (X + blk * (LL * DD))
                                      : (Y + (blk - AP) * (LL * DD));
        const float4 hi = *reinterpret_cast<const float4*>(src + (i + 1) * DD + 4 * d4);
        const float4 lo = *reinterpret_cast<const float4*>(src + i * DD + 4 * d4);
        v = make_float4(hi.x - lo.x, hi.y - lo.y, hi.z - lo.z, hi.w - lo.w);
    }
    *reinterpret_cast<float4*>(g_dZ + (size_t)row * 64 + 4 * d4) = v;
}

// ---------------------------------------------------------------------------
// decode triangular tile index -> (t, u), u >= t
// ---------------------------------------------------------------------------
__device__ __forceinline__ void decode_tile(int tile, int& t, int& u) {
    int q = tile;
    int tt = 0;
    while (q >= NTILE - tt) { q -= NTILE - tt; tt++; }
    t = tt; u = tt + q;
}

// ---------------------------------------------------------------------------
// Combined kernel: producer CTAs (blockIdx < NTRI) run the SYRK tile and
// publish a ready flag; consumer CTAs spin on flags and run the Goursat PDE
// scan on the just-written (L2-hot) inc blocks. Last consumer CTA reduces.
// ---------------------------------------------------------------------------
__global__ void __launch_bounds__(256, 2) combined_kernel(
    const float* __restrict__ X, const float* __restrict__ Y,
    float* __restrict__ out)
{
    extern __shared__ float smem[];
    const int tid  = threadIdx.x;
    const int lane = tid & 31;
    const int wid  = tid >> 5;

    if (blockIdx.x < NTRI) {
        // ================= producer: SYRK tile =============================
        float* sA = smem;                       // [64][SA_STRIDE]
        float* sB = smem + 64 * SA_STRIDE;      // [64][SB_STRIDE]

        const int tile = blockIdx.x;
        int t, u;
        decode_tile(tile, t, u);
        const int gr0 = t * 128;
        const int gc0 = u * 128;

        for (int idx = tid; idx < 128 * 64; idx += 256) {
            const int m = idx >> 6;
            const int k = idx & 63;
            sA[k * SA_STRIDE + m] = g_dZ[(size_t)(gr0 + m) * 64 + k];
            sB[k * SB_STRIDE + m] = g_dZ[(size_t)(gc0 + m) * 64 + k];
        }
        __syncthreads();

        const int ty = tid >> 4;     // 0..15
        const int tx = tid & 15;     // 0..15
        const int m0 = ty * 8;
        const int n0 = 2 * tx;

        unsigned long long acc[8][4];
#pragma unroll
        for (int i = 0; i < 8; i++)
#pragma unroll
            for (int j = 0; j < 4; j++) acc[i][j] = 0ull;

        const float* sA_ = sA + m0;
        const float* sB_ = sB + n0;

#pragma unroll 8
        for (int k = 0; k < 64; k++) {
            unsigned long long aa[8], bb[4];
#pragma unroll
            for (int i = 0; i < 8; i++) {
                const float a = sA_[k * SA_STRIDE + i];
                asm("mov.b64 %0, {%1, %1};" : "=l"(aa[i]) : "f"(a));
            }
#pragma unroll
            for (int j = 0; j < 4; j++)
                bb[j] = *reinterpret_cast<const unsigned long long*>(
                            &sB_[k * SB_STRIDE + 32 * j]);
#pragma unroll
            for (int i = 0; i < 8; i++)
#pragma unroll
                for (int j = 0; j < 4; j++)
                    asm("fma.rn.f32x2 %0, %1, %2, %0;"
                        : "+l"(acc[i][j]) : "l"(aa[i]), "l"(bb[j]));
        }

        // epilogue: scatter sub-blocks to g_inc[tile*4 + sub]
        const int r   = ty >> 3;
        const int li0 = m0 & 63;
#pragma unroll
        for (int c = 0; c < 2; c++) {
            const int pa = 2 * t + r;
            const int pb = 2 * u + c;
            if (pa > pb) continue;        // only (r=1,c=0) on diagonal tiles
            float* dst = g_inc + ((size_t)tile * 4 + r * 2 + c) * BLK_ELEMS;
#pragma unroll
            for (int i = 0; i < 8; i++) {
                float* row = dst + (li0 + i) * 64 + n0;
#pragma unroll
                for (int j = 0; j < 2; j++)
                    *reinterpret_cast<float2*>(row + 32 * j) =
                        *reinterpret_cast<float2*>(&acc[i][2 * c + j]);
            }
        }

        // publish: all writes visible, then release-store the flag
        __threadfence();
        __syncthreads();
        if (tid == 0) {
            unsigned one = 1u;
            asm volatile("st.global.release.gpu.u32 [%0], %1;"
                         :: "l"(&g_flag[tile]), "r"(one) : "memory");
        }
        return;
    }

    // ==================== consumer: Goursat PDE ============================
    {
        const int cidx = blockIdx.x - NTRI;          // 0..PDE_CTAS-1
        const int tile = 2 * cidx + (wid >> 2);      // 2 tiles per CTA
        const int sub  = wid & 3;
        const int r = sub >> 1, c = sub & 1;

        int t, u;
        decode_tile(tile, t, u);
        const int pa = 2 * t + r;
        const int pb = 2 * u + c;

        if (pa <= pb) {
            // wait for producer (acquire)
            const unsigned* fl = &g_flag[tile];
            if (lane == 0) {
                unsigned v;
                do {
                    asm volatile("ld.global.acquire.gpu.u32 %0, [%1];"
                                 : "=r"(v) : "l"(fl) : "memory");
                    if (!v) __nanosleep(256);
                } while (!v);
            }
            __syncwarp();
            __threadfence();   // order subsequent loads after observed flag

            float w;
            if (pa < AP && pb >= AP) w = -2.0f / (float)PER_GRAM;       // XY
            else w = ((pa == pb) ? 1.0f : 2.0f) / (float)PER_GRAM;      // XX/YY

            const float* __restrict__ base =
                g_inc + ((size_t)tile * 4 + sub) * BLK_ELEMS + 2 * lane;
            const bool lastl = (lane == 31);

            float p0 = 1.0f, p1 = 1.0f;

            float2 buf[4];
#pragma unroll
            for (int k = 0; k < 4; k++)
                buf[k] = *reinterpret_cast<const float2*>(base + k * 64);

#pragma unroll 4
            for (int i = 0; i < MM; i++) {
                const float2 inc = buf[i & 3];
                if (i + 4 < MM)
                    buf[i & 3] = *reinterpret_cast<const float2*>(
                                     base + (i + 4) * 64);

                const float p2 = __shfl_down_sync(0xffffffffu, p0, 1);

                const float c0 = fmaf(p0, inc.x - 1.0f, p1);
                const float c1 = lastl ? 0.0f : fmaf(p1, inc.y - 1.0f, p2);

                const float sm = c0 + c1;
                float tc = sm;
#pragma unroll
                for (int off = 1; off < 32; off <<= 1) {
                    const float uu = __shfl_up_sync(0xffffffffu, tc, off);
                    if (lane >= off) tc += uu;
                }
                p0 = 1.0f + (tc - sm);        // exclusive scan
                p1 = p0 + c0;
            }

            if (lastl) g_Ks[tile * 4 + sub] = w * p1;   // weighted K[63][63]
        }
    }

    // ---- final reduction: last consumer CTA sums g_Ks + start term --------
    __threadfence();
    __syncthreads();
    __shared__ bool s_is_last;
    if (tid == 0)
        s_is_last = (atomicAdd(&g_ctr, 1u) == (unsigned)(PDE_CTAS - 1));
    __syncthreads();
    if (!s_is_last) return;

    __shared__ float sdata[256];
    float s = 0.0f;
    for (int p = tid; p < NK2; p += 256) s += __ldcg(&g_Ks[p]);

    float s2 = 0.0f;
    for (int idx = tid; idx < AP * DD; idx += 256) {
        const int aa = idx >> 6;
        const int d  = idx & 63;
        const float diff = X[aa * (LL * DD) + d] - Y[aa * (LL * DD) + d];
        s2 = fmaf(diff, diff, s2);
    }
    s += s2 * (1.0f / (float)(AP * DD));

    sdata[tid] = s;
    __syncthreads();
    for (int k = 128; k > 0; k >>= 1) {
        if (tid < k) sdata[tid] += sdata[tid + k];
        __syncthreads();
    }
    if (tid == 0) out[0] = sdata[0];
}

// ---------------------------------------------------------------------------
extern "C" void kernel_launch(void* const* d_in, const int* in_sizes, int n_in,
                              void* d_out, int out_size)
{
    const float* X = (const float*)d_in[0];
    const float* Y = (const float*)d_in[1];
    float* out = (float*)d_out;

    static bool attr_done = false;
    if (!attr_done) {
        cudaFuncSetAttribute(combined_kernel,
                             cudaFuncAttributeMaxDynamicSharedMemorySize,
                             SMEM_BYTES);
        attr_done = true;
    }

    dz_kernel<<<384, 256>>>(X, Y);
    combined_kernel<<<TOTAL_CTAS, 256, SMEM_BYTES>>>(X, Y, out);
}

// round 15
// speedup vs baseline: 1.3893x; 1.3495x over previous
#include <cuda_runtime.h>
#include <cuda_bf16.h>
#include <cstdint>

// Problem constants
#define AP 48        // paths
#define LL 64        // length
#define DD 64        // channels
#define MM 63        // L-1 (increments)
#define PER_GRAM (AP*AP)          // 2304

#define NPB 96                    // 48 X blocks + 48 Y blocks (64 padded rows)
#define ROWS (NPB*64)             // 6144
#define NTILE 48                  // tiles per dim (128 rows each)
#define NTRI (NTILE*(NTILE+1)/2)  // 1176 upper-triangle tiles
#define NK2 (NTRI*4)              // 4704 (tile, sub) result slots

// Static scratch. g_Ks zero-init; inactive diagonal sub-slots stay 0.
__device__ __nv_bfloat16 g_dZhi[(size_t)ROWS * 64];   // split increments (hi)
__device__ __nv_bfloat16 g_dZlo[(size_t)ROWS * 64];   // split increments (lo)
__device__ float g_Ks[NK2];
__device__ unsigned g_ctr;

// smem: mma phase  4 tiles [128 rows][36 b32]  (72 bf16/row, conflict-free)
//       pde phase  sT = 4 sub-blocks [64][66] floats (aliases)
#define ASTRW 36                       // b32 per row
#define TILE_U32 (128*ASTRW)           // 4608
#define TSTR 66
#define SUB_FLOATS (64*TSTR)
#define DYN_BYTES (4*TILE_U32*4)       // 73728 B

// ---------------------------------------------------------------------------
// Kernel 0: split-bf16 padded increments + counter reset.
// ---------------------------------------------------------------------------
__global__ void __launch_bounds__(256) dz_kernel(
    const float* __restrict__ X, const float* __restrict__ Y)
{
    const int gi = blockIdx.x * 256 + threadIdx.x;    // 98304 = 6144*16
    if (gi == 0) g_ctr = 0u;

    const int row = gi >> 4;
    const int d4  = gi & 15;
    const int blk = row >> 6;
    const int i   = row & 63;

    float4 v = make_float4(0.f, 0.f, 0.f, 0.f);
    if (i < MM) {
        const float* src = (blk < AP) ? (X + blk * (LL * DD))
                                      : (Y + (blk - AP) * (LL * DD));
        const float4 hi = *reinterpret_cast<const float4*>(src + (i + 1) * DD + 4 * d4);
        const float4 lo = *reinterpret_cast<const float4*>(src + i * DD + 4 * d4);
        v = make_float4(hi.x - lo.x, hi.y - lo.y, hi.z - lo.z, hi.w - lo.w);
    }

    __nv_bfloat16 h[4], l[4];
    const float vv[4] = {v.x, v.y, v.z, v.w};
#pragma unroll
    for (int c = 0; c < 4; c++) {
        h[c] = __float2bfloat16(vv[c]);
        l[c] = __float2bfloat16(vv[c] - __bfloat162float(h[c]));
    }
    __nv_bfloat162* dh = reinterpret_cast<__nv_bfloat162*>(g_dZhi) + row * 32 + 2 * d4;
    __nv_bfloat162* dl = reinterpret_cast<__nv_bfloat162*>(g_dZlo) + row * 32 + 2 * d4;
    dh[0] = __nv_bfloat162(h[0], h[1]);
    dh[1] = __nv_bfloat162(h[2], h[3]);
    dl[0] = __nv_bfloat162(l[0], l[1]);
    dl[1] = __nv_bfloat162(l[2], l[3]);
}

// ---------------------------------------------------------------------------
// Fused kernel: per 128x128 tile (u >= t):
//   phase 1: split-bf16 mma.sync SYRK (8 warps x 16 rows x 128 cols)
//   phase 2: epilogue to smem sub-blocks [64][66]
//   phase 3: warps 0-3 run wavefront Goursat PDE
//   phase 4: last CTA reduces
// ---------------------------------------------------------------------------
__global__ void __launch_bounds__(256, 2) sig_kernel(
    const float* __restrict__ X, const float* __restrict__ Y,
    float* __restrict__ out)
{
    extern __shared__ uint32_t smw[];
    uint32_t* sAhi = smw;
    uint32_t* sAlo = smw + TILE_U32;
    uint32_t* sBhi = smw + 2 * TILE_U32;
    uint32_t* sBlo = smw + 3 * TILE_U32;
    float*    sT   = reinterpret_cast<float*>(smw);   // pde phase alias

    const int tid  = threadIdx.x;
    const int lane = tid & 31;
    const int wid  = tid >> 5;
    const int gid  = lane >> 2;     // 0..7
    const int tig  = lane & 3;      // 0..3

    int q = blockIdx.x, t = 0;
    while (q >= NTILE - t) { q -= NTILE - t; t++; }
    const int u = t + q;
    const int gr0 = t * 128;
    const int gc0 = u * 128;

    // ---- phase 0: load split tiles into smem (coalesced, conflict-free) ---
    {
        const uint32_t* gh = reinterpret_cast<const uint32_t*>(g_dZhi);
        const uint32_t* gl = reinterpret_cast<const uint32_t*>(g_dZlo);
        for (int idx = tid; idx < 128 * 32; idx += 256) {
            const int m = idx >> 5;
            const int c = idx & 31;
            const int ia = (gr0 + m) * 32 + c;
            const int ib = (gc0 + m) * 32 + c;
            sAhi[m * ASTRW + c] = gh[ia];
            sAlo[m * ASTRW + c] = gl[ia];
            sBhi[m * ASTRW + c] = gh[ib];
            sBlo[m * ASTRW + c] = gl[ib];
        }
    }
    __syncthreads();

    // ---- phase 1: mma.sync mainloop ---------------------------------------
    // warp wid: output rows mb..mb+15, all 128 cols (16 n-tiles of m16n8).
    const int mb = wid * 16;
    float c[16][4];
#pragma unroll
    for (int j = 0; j < 16; j++)
#pragma unroll
        for (int e = 0; e < 4; e++) c[j][e] = 0.0f;

#pragma unroll
    for (int ks = 0; ks < 4; ks++) {
        const int kc0 = 8 * ks + tig;   // b32 col, k-lo half
        const int kc1 = kc0 + 4;        // k-hi half (+8 bf16)
        const int ar0 = (mb + gid) * ASTRW;
        const int ar1 = (mb + gid + 8) * ASTRW;

        const uint32_t ah0 = sAhi[ar0 + kc0], ah1 = sAhi[ar1 + kc0];
        const uint32_t ah2 = sAhi[ar0 + kc1], ah3 = sAhi[ar1 + kc1];
        const uint32_t al0 = sAlo[ar0 + kc0], al1 = sAlo[ar1 + kc0];
        const uint32_t al2 = sAlo[ar0 + kc1], al3 = sAlo[ar1 + kc1];

#pragma unroll
        for (int j = 0; j < 16; j++) {
            const int br = (8 * j + gid) * ASTRW;
            const uint32_t bh0 = sBhi[br + kc0], bh1 = sBhi[br + kc1];
            const uint32_t bl0 = sBlo[br + kc0], bl1 = sBlo[br + kc1];

            asm volatile(
                "mma.sync.aligned.m16n8k16.row.col.f32.bf16.bf16.f32 "
                "{%0,%1,%2,%3}, {%4,%5,%6,%7}, {%8,%9}, {%0,%1,%2,%3};"
                : "+f"(c[j][0]), "+f"(c[j][1]), "+f"(c[j][2]), "+f"(c[j][3])
                : "r"(ah0), "r"(ah1), "r"(ah2), "r"(ah3), "r"(bh0), "r"(bh1));
            asm volatile(
                "mma.sync.aligned.m16n8k16.row.col.f32.bf16.bf16.f32 "
                "{%0,%1,%2,%3}, {%4,%5,%6,%7}, {%8,%9}, {%0,%1,%2,%3};"
                : "+f"(c[j][0]), "+f"(c[j][1]), "+f"(c[j][2]), "+f"(c[j][3])
                : "r"(ah0), "r"(ah1), "r"(ah2), "r"(ah3), "r"(bl0), "r"(bl1));
            asm volatile(
                "mma.sync.aligned.m16n8k16.row.col.f32.bf16.bf16.f32 "
                "{%0,%1,%2,%3}, {%4,%5,%6,%7}, {%8,%9}, {%0,%1,%2,%3};"
                : "+f"(c[j][0]), "+f"(c[j][1]), "+f"(c[j][2]), "+f"(c[j][3])
                : "r"(al0), "r"(al1), "r"(al2), "r"(al3), "r"(bh0), "r"(bh1));
        }
    }
    __syncthreads();   // everyone done reading A/B smem

    // ---- phase 2: epilogue to sT sub-blocks [64][TSTR] --------------------
    // D layout: c0=D[gid][2tig], c1=D[gid][2tig+1], c2=D[gid+8][2tig], c3=+1
    {
        const int subr = wid >> 2;          // row sub-block
        const int lr0  = (mb & 63) + gid;
        const int lr1  = lr0 + 8;
#pragma unroll
        for (int j = 0; j < 16; j++) {
            const int nb  = 8 * j;
            const int sub = subr * 2 + (nb >> 6);
            const int col = (nb & 63) + 2 * tig;
            float* d0 = sT + sub * SUB_FLOATS + lr0 * TSTR + col;
            float* d1 = sT + sub * SUB_FLOATS + lr1 * TSTR + col;
            *reinterpret_cast<float2*>(d0) = make_float2(c[j][0], c[j][1]);
            *reinterpret_cast<float2*>(d1) = make_float2(c[j][2], c[j][3]);
        }
    }
    __syncthreads();

    // ---- phase 3: wavefront Goursat PDE, warp sub = wid (0..3) ------------
    // K[r][c] = K[r][c-1] + K[r-1][c] + K[r-1][c-1]*(inc[r-1][c-1]-1).
    // Lane l owns cols c0=2l, c1=2l+1; 2-row block b at step s = l + b.
    if (wid < 4) {
        const int sr = wid >> 1, sc = wid & 1;
        const int pa = 2 * t + sr;
        const int pb = 2 * u + sc;
        if (pa <= pb) {
            float w;
            if (pa < AP && pb >= AP) w = -2.0f / (float)PER_GRAM;       // XY
            else w = ((pa == pb) ? 1.0f : 2.0f) / (float)PER_GRAM;      // XX/YY

            const float* base = sT + wid * SUB_FLOATS;
            const int c0  = 2 * lane;
            const int cm1 = (c0 == 0) ? 0 : (c0 - 1);
            const bool lane0 = (lane == 0);

            float t0 = 1.0f, t1 = 1.0f;
            float y0 = 1.0f, z = 1.0f;

#pragma unroll 1
            for (int s = 0; s < 63; s++) {
                const float ny0 = __shfl_up_sync(0xffffffffu, y0, 1);
                const float nt1 = __shfl_up_sync(0xffffffffu, t1, 1);
                const float nz  = __shfl_up_sync(0xffffffffu, z, 1);

                const int b = s - lane;
                const bool act  = (b >= 0) & (b <= 31);
                const bool row2 = (b >= 0) & (b <= 30);

                if (act) {
                    const int r0 = 2 * b + 1;
                    const float* rp = base + (r0 - 1) * TSTR;
                    const float i00 = rp[cm1];
                    const float i01 = rp[c0];
                    const float i10 = rp[TSTR + cm1];
                    const float i11 = rp[TSTR + c0];

                    const float zp = t1;

                    const float A = lane0 ? 1.0f : fmaf(nz, i00 - 1.0f, ny0 + t0);
                    const float B = fmaf(t0, i01 - 1.0f, A + t1);

                    if (row2) {
                        const float C = lane0 ? 1.0f : fmaf(ny0, i10 - 1.0f, nt1 + A);
                        const float D = fmaf(A, i11 - 1.0f, C + B);
                        t0 = C; t1 = D;
                    } else {
                        t0 = A; t1 = B;
                    }
                    y0 = B; z = zp;
                }
            }

            if (lane == 31)
                g_Ks[blockIdx.x * 4 + wid] = w * y0;   // K[63][63], weighted
        }
    }

    // ---- phase 4: last CTA reduces ----------------------------------------
    __threadfence();
    __syncthreads();
    __shared__ bool s_is_last;
    if (tid == 0)
        s_is_last = (atomicAdd(&g_ctr, 1u) == (unsigned)(gridDim.x - 1));
    __syncthreads();
    if (!s_is_last) return;

    __shared__ float sdata[256];
    float s = 0.0f;
    for (int p = tid; p < NK2; p += 256) s += __ldcg(&g_Ks[p]);

    float s2 = 0.0f;
    for (int idx = tid; idx < AP * DD; idx += 256) {
        const int aa = idx >> 6;
        const int d  = idx & 63;
        const float diff = X[aa * (LL * DD) + d] - Y[aa * (LL * DD) + d];
        s2 = fmaf(diff, diff, s2);
    }
    s += s2 * (1.0f / (float)(AP * DD));

    sdata[tid] = s;
    __syncthreads();
    for (int k = 128; k > 0; k >>= 1) {
        if (tid < k) sdata[tid] += sdata[tid + k];
        __syncthreads();
    }
    if (tid == 0) out[0] = sdata[0];
}

// ---------------------------------------------------------------------------
extern "C" void kernel_launch(void* const* d_in, const int* in_sizes, int n_in,
                              void* d_out, int out_size)
{
    const float* X = (const float*)d_in[0];
    const float* Y = (const float*)d_in[1];
    float* out = (float*)d_out;

    static bool attr_done = false;
    if (!attr_done) {
        cudaFuncSetAttribute(sig_kernel,
                             cudaFuncAttributeMaxDynamicSharedMemorySize,
                             DYN_BYTES);
        attr_done = true;
    }

    dz_kernel<<<384, 256>>>(X, Y);
    sig_kernel<<<NTRI, 256, DYN_BYTES>>>(X, Y, out);
}